// round 17
// baseline (speedup 1.0000x reference)
#include <cuda_runtime.h>
#include <cuda_fp16.h>
#include <stdint.h>

// Problem constants (B=1, N=256, L=192, J=32, d2=1024, F=128)
#define LDIM 192
#define NDIM 256      // K of GEMM1
#define RDIM 6144     // L*J  (M=N of GEMM1)
#define D2   1024     // J*J  (K of GEMM2)
#define FDIM 128      // N of GEMM2
#define M2   36864    // L*L  (M of GEMM2)

// ---------------------------------------------------------------------------
// Scratch (__device__ globals), ALL single fp16, K-BLOCKED layouts:
//   g_A / g_B : [n-chunk 0..7][row 0..6143][32 fp16]   (chunk block = 384 KB)
//   g_P       : [j 0..31][row 0..36863][32 fp16]        (chunk block = 2.25 MB)
//   g_Wt      : [k-chunk 0..31][f 0..127][32 fp16]      (chunk block = 8 KB)
// A 32-K chunk slice for one CTA (128 rows x 64B) is CONTIGUOUS 8 KB.
// ---------------------------------------------------------------------------
__device__ __half g_A[(size_t)RDIM * 256];
__device__ __half g_B[(size_t)RDIM * 256];
__device__ __half g_P[(size_t)M2 * 1024];
__device__ __half g_Wt[(size_t)FDIM * 1024];
__device__ float g_mu[M2];
__device__ float g_rs[M2];
__device__ float g_c1[FDIM];
__device__ float g_c2[FDIM];

// ---------------------------------------------------------------------------
// Family-portable PTX helpers (compute_103-safe)
// ---------------------------------------------------------------------------
__device__ __forceinline__ uint32_t smem_u32(const void* p) {
    uint32_t a;
    asm("{ .reg .u64 t; cvta.to.shared.u64 t, %1; cvt.u32.u64 %0, t; }" : "=r"(a) : "l"(p));
    return a;
}
__device__ __forceinline__ void cp16(uint32_t dst, const void* src) {
    asm volatile("cp.async.cg.shared.global [%0], [%1], 16;" :: "r"(dst), "l"(src) : "memory");
}
__device__ __forceinline__ void cp_commit() {
    asm volatile("cp.async.commit_group;" ::: "memory");
}
template <int N>
__device__ __forceinline__ void cp_wait() {
    asm volatile("cp.async.wait_group %0;" :: "n"(N) : "memory");
}
__device__ __forceinline__ void ldm4(uint32_t a[4], uint32_t addr) {
    asm volatile("ldmatrix.sync.aligned.m8n8.x4.shared.b16 {%0,%1,%2,%3}, [%4];"
                 : "=r"(a[0]), "=r"(a[1]), "=r"(a[2]), "=r"(a[3]) : "r"(addr));
}
__device__ __forceinline__ void ldm2(uint32_t b[2], uint32_t addr) {
    asm volatile("ldmatrix.sync.aligned.m8n8.x2.shared.b16 {%0,%1}, [%2];"
                 : "=r"(b[0]), "=r"(b[1]) : "r"(addr));
}
// fp16 inputs, fp32 accumulate
__device__ __forceinline__ void mma16816(float c[4], const uint32_t a[4], const uint32_t b[2]) {
    asm volatile(
        "mma.sync.aligned.m16n8k16.row.col.f32.f16.f16.f32 "
        "{%0,%1,%2,%3}, {%4,%5,%6,%7}, {%8,%9}, {%0,%1,%2,%3};"
        : "+f"(c[0]), "+f"(c[1]), "+f"(c[2]), "+f"(c[3])
        : "r"(a[0]), "r"(a[1]), "r"(a[2]), "r"(a[3]), "r"(b[0]), "r"(b[1]));
}

// SMEM subtile: 128 rows x 16 fp16 (32B/row), 2x16B chunks.
// Swizzle: chunk bit XOR (r>>2)&1 -> conflict-free ldmatrix phases.
__device__ __forceinline__ uint32_t sw(int r, int c2) {
    return (uint32_t)(r * 32 + ((c2 ^ ((r >> 2) & 1)) << 4));
}

// Stage (16 KB) = 32-K worth: [A_k0 | A_k1 | B_k0 | B_k1] (4KB subtiles)
#define STAGE_BYTES 16384
#define NSTAGE 3
#define SMEM_BYTES  (NSTAGE * STAGE_BYTES)   // 48 KB static, 2 CTAs/SM

// ---------------------------------------------------------------------------
// Shared mainloop: 128x128 CTA tile, 8 warps (2x4), warp tile 64x32,
// 32-K per iteration, 3-stage ring (prefetch distance 2), one wait + one
// barrier per 32-K. K-blocked gmem layout: thread t reads the CONTIGUOUS
// 32B at (chunk block) + t*32 (= row t>>1, k-half t&1) -> warp covers 1KB
// dense (nL=8, no wasted sectors). ACS/BCS = bytes per k-chunk block.
// ---------------------------------------------------------------------------
template <int ACS, int BCS>
__device__ __forceinline__ void mainloop(
    uint32_t sb, int NC32,
    const char* __restrict__ A, const char* __restrict__ B,
    float acc[4][4][4])
{
    const int tid = threadIdx.x, lane = tid & 31;
    const int wr = tid >> 7;           // warp row 0..1 (64 rows each)
    const int wc = (tid >> 5) & 3;     // warp col 0..3 (32 cols each)

    // k-blocked fetch: thread t owns row t>>1, k-half t&1 (32B contiguous).
    const int h = tid & 1;
    const char* pA = A + (size_t)tid * 32;
    const char* pB = B + (size_t)tid * 32;
    const uint32_t dh0 = (uint32_t)h * 4096u + sw(tid >> 1, 0);
    const uint32_t dh1 = (uint32_t)h * 4096u + sw(tid >> 1, 1);

    // ldmatrix fragment base offsets (+512/+256 shift rows by 16/8: parity safe).
    const uint32_t abase = sw(wr * 64 + (lane & 15), lane >> 4);
    const uint32_t bbase = sw(wc * 32 + (lane & 7), (lane >> 3) & 1);

#define ISSUE_CHUNK(ck, st) do {                                     \
        uint32_t _b = sb + (uint32_t)(st) * STAGE_BYTES;             \
        const char* _a = pA + (size_t)(ck) * ACS;                    \
        const char* _bp = pB + (size_t)(ck) * BCS;                   \
        cp16(_b + dh0,          _a);                                 \
        cp16(_b + dh1,          _a + 16);                            \
        cp16(_b + 8192u + dh0,  _bp);                                \
        cp16(_b + 8192u + dh1,  _bp + 16);                           \
    } while (0)

    // prologue: chunks 0,1 -> stages 0,1
    ISSUE_CHUNK(0, 0); cp_commit();
    if (NC32 > 1) ISSUE_CHUNK(1, 1);
    cp_commit();

#pragma unroll 1
    for (int c = 0; c < NC32; ++c) {
        const int st = c % NSTAGE;
        cp_wait<1>();          // chunk c resident (c+1 may still be in flight)
        __syncthreads();       // all warps finished reading stage (c-1)%3

        if (c + 2 < NC32) ISSUE_CHUNK(c + 2, (c + 2) % NSTAGE);
        cp_commit();

        const uint32_t Ab = sb + (uint32_t)st * STAGE_BYTES;
#pragma unroll
        for (int k = 0; k < 2; ++k) {
            const uint32_t Ak = Ab + (uint32_t)k * 4096u;
            const uint32_t Bk = Ab + 8192u + (uint32_t)k * 4096u;

            uint32_t bf[4][2];
#pragma unroll
            for (int nt = 0; nt < 4; ++nt) ldm2(bf[nt], Bk + bbase + nt * 256u);
#pragma unroll
            for (int mt = 0; mt < 4; ++mt) {
                uint32_t a[4];
                ldm4(a, Ak + abase + mt * 512u);
#pragma unroll
                for (int nt = 0; nt < 4; ++nt) mma16816(acc[mt][nt], a, bf[nt]);
            }
        }
    }
#undef ISSUE_CHUNK
}

// ---------------------------------------------------------------------------
// GEMM1: pair(6144x6144) = Xd^T Xw, K=256. Epilogue: LN stats per 32x32
// (i,l) block + pair stored single fp16, K-BLOCKED [j][row][32].
// ---------------------------------------------------------------------------
__global__ __launch_bounds__(256, 2) void gemm1_mma() {
    __shared__ char smem[SMEM_BYTES];
    const uint32_t sb = smem_u32(smem);

    float acc[4][4][4];
#pragma unroll
    for (int a = 0; a < 4; ++a)
#pragma unroll
        for (int b = 0; b < 4; ++b)
#pragma unroll
            for (int d = 0; d < 4; ++d) acc[a][b][d] = 0.f;

    const int r0 = blockIdx.y * 128, c0 = blockIdx.x * 128;
    mainloop<RDIM * 64, RDIM * 64>(sb, NDIM / 32,
                                   (const char*)g_A + (size_t)r0 * 64,
                                   (const char*)g_B + (size_t)c0 * 64, acc);

    const int tid = threadIdx.x, lane = tid & 31;
    const int wr = tid >> 7, wc = (tid >> 5) & 3;

    // Warp covers rows wr*64..+63 (2 LN i-blocks), cols wc*32..+31 (1 l-block).
#pragma unroll
    for (int b = 0; b < 2; ++b) {
        float s = 0.f, q = 0.f;
#pragma unroll
        for (int mt2 = 0; mt2 < 2; ++mt2)
#pragma unroll
            for (int nt = 0; nt < 4; ++nt)
#pragma unroll
                for (int d = 0; d < 4; ++d) {
                    float v = acc[b * 2 + mt2][nt][d];
                    s += v;
                    q += v * v;
                }
#pragma unroll
        for (int o = 16; o; o >>= 1) {
            s += __shfl_xor_sync(0xFFFFFFFFu, s, o);
            q += __shfl_xor_sync(0xFFFFFFFFu, q, o);
        }
        const int i = blockIdx.y * 4 + wr * 2 + b;
        const int l = blockIdx.x * 4 + wc;
        if (lane == 0) {
            float mean = s * (1.0f / 1024.0f);
            float var = q * (1.0f / 1024.0f) - mean * mean;
            g_mu[i * LDIM + l] = mean;
            g_rs[i * LDIM + l] = rsqrtf(var + 1e-5f);
        }
        const size_t rowoff = (size_t)(i * LDIM + l) * 32;   // within j-block
#pragma unroll
        for (int mt2 = 0; mt2 < 2; ++mt2)
#pragma unroll
            for (int nt = 0; nt < 4; ++nt)
#pragma unroll
                for (int h = 0; h < 2; ++h) {
                    float v0 = acc[b * 2 + mt2][nt][h * 2 + 0];
                    float v1 = acc[b * 2 + mt2][nt][h * 2 + 1];
                    int j = mt2 * 16 + (lane >> 2) + 8 * h;
                    int m = nt * 8 + (lane & 3) * 2;
                    __half2 hh = __floats2half2_rn(v0, v1);
                    *(uint32_t*)(g_P + (size_t)j * (M2 * 32) + rowoff + m) = *(uint32_t*)&hh;
                }
    }
}

// ---------------------------------------------------------------------------
// GEMM2: out(36864x128) = pair @ Wp, K=1024. Epilogue: folded layernorm.
// ---------------------------------------------------------------------------
__global__ __launch_bounds__(256, 2) void gemm2_mma(float* __restrict__ out) {
    __shared__ char smem[SMEM_BYTES];
    const uint32_t sb = smem_u32(smem);

    float acc[4][4][4];
#pragma unroll
    for (int a = 0; a < 4; ++a)
#pragma unroll
        for (int b = 0; b < 4; ++b)
#pragma unroll
            for (int d = 0; d < 4; ++d) acc[a][b][d] = 0.f;

    const int row0 = blockIdx.x * 128;
    mainloop<M2 * 64, FDIM * 64>(sb, D2 / 32,
                                 (const char*)g_P + (size_t)row0 * 64,
                                 (const char*)g_Wt, acc);

    const int tid = threadIdx.x, lane = tid & 31;
    const int wr = tid >> 7, wc = (tid >> 5) & 3;

    float c1v[4][2], c2v[4][2];
#pragma unroll
    for (int nt = 0; nt < 4; ++nt)
#pragma unroll
        for (int e = 0; e < 2; ++e) {
            int f = wc * 32 + nt * 8 + (lane & 3) * 2 + e;
            c1v[nt][e] = g_c1[f];
            c2v[nt][e] = g_c2[f];
        }
#pragma unroll
    for (int mt = 0; mt < 4; ++mt)
#pragma unroll
        for (int h = 0; h < 2; ++h) {
            int rr = row0 + wr * 64 + mt * 16 + (lane >> 2) + 8 * h;
            float rs = g_rs[rr];
            float tmu = rs * g_mu[rr];
#pragma unroll
            for (int nt = 0; nt < 4; ++nt) {
                float2 o;
                o.x = rs * acc[mt][nt][h * 2 + 0] - tmu * c1v[nt][0] + c2v[nt][0];
                o.y = rs * acc[mt][nt][h * 2 + 1] - tmu * c1v[nt][1] + c2v[nt][1];
                *(float2*)(out + (size_t)rr * FDIM + wc * 32 + nt * 8 + (lane & 3) * 2) = o;
            }
        }
}

// ---------------------------------------------------------------------------
// Prep (merged): z=0 -> x_down^T -> g_A; z=1 -> x_down_w^T -> g_B;
// z=2 (x<32, y<4 only) -> (a2*W)^T -> g_Wt. All k-blocked layouts.
// ---------------------------------------------------------------------------
__global__ __launch_bounds__(256) void prep_split(const float* __restrict__ xd,
                                                  const float* __restrict__ xw,
                                                  const float* __restrict__ W,
                                                  const float* __restrict__ a2) {
    __shared__ float t[32][33];
    const int tx = threadIdx.x & 31, ty = threadIdx.x >> 5;

    if (blockIdx.z < 2) {
        const float* src = blockIdx.z ? xw : xd;
        __half* dst = blockIdx.z ? g_B : g_A;
        const int r0 = blockIdx.x * 32, n0 = blockIdx.y * 32;
#pragma unroll
        for (int yy = 0; yy < 4; ++yy) {
            int n = n0 + ty + yy * 8;
            t[ty + yy * 8][tx] = src[(size_t)n * RDIM + r0 + tx];
        }
        __syncthreads();
        // k-blocked: [n-chunk = blockIdx.y][row r][n&31 = tx]
        const size_t blk = (size_t)blockIdx.y * (RDIM * 32);
#pragma unroll
        for (int yy = 0; yy < 4; ++yy) {
            int r = r0 + ty + yy * 8;
            dst[blk + (size_t)r * 32 + tx] = __float2half_rn(t[tx][ty + yy * 8]);
        }
    } else {
        if (blockIdx.x >= 32 || blockIdx.y >= 4) return;
        const int k0 = blockIdx.x * 32, f0 = blockIdx.y * 32;
#pragma unroll
        for (int yy = 0; yy < 4; ++yy) {
            int k = k0 + ty + yy * 8;
            t[ty + yy * 8][tx] = a2[k] * W[(size_t)k * FDIM + f0 + tx];
        }
        __syncthreads();
        // k-blocked: [k-chunk = blockIdx.x][f][k&31 = tx]
        const size_t blk = (size_t)blockIdx.x * (FDIM * 32);
#pragma unroll
        for (int yy = 0; yy < 4; ++yy) {
            int f = f0 + ty + yy * 8;
            g_Wt[blk + (size_t)f * 32 + tx] = __float2half_rn(t[tx][ty + yy * 8]);
        }
    }
}

// Prep: c1[f] = sum_k a2[k] W[k][f]; c2[f] = sum_k b2[k] W[k][f] + b[f].
// One 1024-thread block: f = t&127, k-slice = t>>7; coalesced, deterministic.
__global__ __launch_bounds__(1024) void prep_c(const float* __restrict__ a2,
                                               const float* __restrict__ b2,
                                               const float* __restrict__ W,
                                               const float* __restrict__ b) {
    __shared__ float s1[8][FDIM], s2[8][FDIM];
    const int f = threadIdx.x & 127, ks = threadIdx.x >> 7;
    const int kbase = ks * 128;
    float c1 = 0.f, c2 = 0.f;
#pragma unroll 8
    for (int kk = 0; kk < 128; ++kk) {
        int k = kbase + kk;
        float w = W[(size_t)k * FDIM + f];
        c1 += a2[k] * w;
        c2 += b2[k] * w;
    }
    s1[ks][f] = c1;
    s2[ks][f] = c2;
    __syncthreads();
    if (ks == 0) {
        float t1 = 0.f, t2 = 0.f;
#pragma unroll
        for (int p = 0; p < 8; ++p) {
            t1 += s1[p][f];
            t2 += s2[p][f];
        }
        g_c1[f] = t1;
        g_c2[f] = t2 + b[f];
    }
}

// ---------------------------------------------------------------------------
extern "C" void kernel_launch(void* const* d_in, const int* in_sizes, int n_in,
                              void* d_out, int out_size) {
    const float* x_down   = (const float*)d_in[0];  // (1,256,192,32)
    const float* x_down_w = (const float*)d_in[1];
    const float* a2       = (const float*)d_in[2];  // (1024,)
    const float* b2       = (const float*)d_in[3];
    const float* W        = (const float*)d_in[4];  // (1024,128)
    const float* b        = (const float*)d_in[5];  // (128,)
    float* out = (float*)d_out;                     // (1,192,192,128)

    // Keep the L1/smem carveout high so two 48KB-smem CTAs co-reside per SM.
    cudaFuncSetAttribute(gemm1_mma, cudaFuncAttributePreferredSharedMemoryCarveout, 100);
    cudaFuncSetAttribute(gemm2_mma, cudaFuncAttributePreferredSharedMemoryCarveout, 100);

    prep_split<<<dim3(RDIM / 32, NDIM / 32, 3), 256>>>(x_down, x_down_w, W, a2);
    prep_c<<<1, 1024>>>(a2, b2, W, b);
    gemm1_mma<<<dim3(48, 48), 256>>>();
    gemm2_mma<<<M2 / 128, 256>>>(out);
}